// round 1
// baseline (speedup 1.0000x reference)
#include <cuda_runtime.h>

// axon_layer: dual-exponential PSP scan.
//   m_t = m_{t-1}*dm + x_t ; s_t = s_{t-1}*ds + x_t ; psp_t = (m_t - s_t)*v0
// Inputs: [0] input_spikes f32 [B,F,T]  [1] decay_m f32 [F]
//         [2] decay_s f32 [F]           [3] v_0 f32 scalar
// Output: psps [B,F,T] followed by m_T [B,F] and s_T [B,F] (tuple flatten order).

#define AX_THREADS 128
#define AX_ROWS    128
#define AX_T       400
#define AX_CHUNK   100          // floats per T-chunk
#define AX_CHUNK4  25           // float4 per T-chunk (odd -> conflict-free LDS.128)
#define AX_NCHUNK  4

__device__ __forceinline__ void ax_cp_async16(void* smem_dst, const void* gmem_src) {
    unsigned saddr = (unsigned)__cvta_generic_to_shared(smem_dst);
    asm volatile("cp.async.cg.shared.global [%0], [%1], 16;\n"
                 :: "r"(saddr), "l"(gmem_src));
}
__device__ __forceinline__ void ax_cp_commit_wait() {
    asm volatile("cp.async.commit_group;\n");
    asm volatile("cp.async.wait_group 0;\n");
}

extern __shared__ float4 ax_tile[];   // AX_ROWS * AX_CHUNK4 float4 = 51200 B

__global__ void __launch_bounds__(AX_THREADS)
axon_layer_kernel(const float* __restrict__ x,
                  const float* __restrict__ decay_m,
                  const float* __restrict__ decay_s,
                  const float* __restrict__ v0p,
                  float* __restrict__ out,
                  int F, long long n_rows, long long out_size)
{
    const int tid = threadIdx.x;
    const long long row0 = (long long)blockIdx.x * AX_ROWS;
    const long long my_row = row0 + tid;

    const float dm = __ldg(&decay_m[(int)(my_row % F)]);
    const float ds = __ldg(&decay_s[(int)(my_row % F)]);
    const float v0 = __ldg(v0p);

    float m = 0.0f, s = 0.0f;

    const float4* __restrict__ gin  = (const float4*)x + row0 * (AX_T / 4);
    float4* __restrict__       gout = (float4*)out     + row0 * (AX_T / 4);

    const int rquads = AX_T / 4;          // 100 float4 per full row
    const int rbase  = tid * AX_CHUNK4;   // this thread's row inside the tile

    for (int ch = 0; ch < AX_NCHUNK; ++ch) {
        const int goff = ch * AX_CHUNK4;

        // ---- stage in (coalesced, cp.async) ----
        #pragma unroll
        for (int i = 0; i < AX_CHUNK4; ++i) {
            int idx = i * AX_THREADS + tid;       // 0..3199 linear over tile
            int r = idx / AX_CHUNK4;
            int c = idx - r * AX_CHUNK4;
            ax_cp_async16(&ax_tile[idx], &gin[(long long)r * rquads + goff + c]);
        }
        ax_cp_commit_wait();
        __syncthreads();

        // ---- sequential scan along T for this thread's row (in-place) ----
        #pragma unroll 5
        for (int t4 = 0; t4 < AX_CHUNK4; ++t4) {
            float4 q = ax_tile[rbase + t4];
            float4 o;
            m = fmaf(m, dm, q.x); s = fmaf(s, ds, q.x); o.x = (m - s) * v0;
            m = fmaf(m, dm, q.y); s = fmaf(s, ds, q.y); o.y = (m - s) * v0;
            m = fmaf(m, dm, q.z); s = fmaf(s, ds, q.z); o.z = (m - s) * v0;
            m = fmaf(m, dm, q.w); s = fmaf(s, ds, q.w); o.w = (m - s) * v0;
            ax_tile[rbase + t4] = o;
        }
        __syncthreads();

        // ---- stage out (coalesced) ----
        #pragma unroll
        for (int i = 0; i < AX_CHUNK4; ++i) {
            int idx = i * AX_THREADS + tid;
            int r = idx / AX_CHUNK4;
            int c = idx - r * AX_CHUNK4;
            gout[(long long)r * rquads + goff + c] = ax_tile[idx];
        }
        __syncthreads();   // tile reused next chunk
    }

    // ---- final state (m_T, s_T) appended after the psps block ----
    const long long psps_elems = n_rows * AX_T;
    if (out_size >= psps_elems + 2 * n_rows) {
        out[psps_elems + my_row]          = m;
        out[psps_elems + n_rows + my_row] = s;
    }
}

extern "C" void kernel_launch(void* const* d_in, const int* in_sizes, int n_in,
                              void* d_out, int out_size)
{
    const float* x   = (const float*)d_in[0];
    const float* dmv = (const float*)d_in[1];
    const float* dsv = (const float*)d_in[2];
    const float* v0p = (const float*)d_in[3];
    float* out = (float*)d_out;

    const int F = in_sizes[1];                        // 4096
    const long long total = (long long)in_sizes[0];   // B*F*T
    const long long n_rows = total / AX_T;            // B*F
    const int grid = (int)(n_rows / AX_ROWS);

    static bool attr_set = false;
    if (!attr_set) {
        cudaFuncSetAttribute(axon_layer_kernel,
                             cudaFuncAttributeMaxDynamicSharedMemorySize,
                             AX_ROWS * AX_CHUNK4 * (int)sizeof(float4));
        attr_set = true;
    }

    axon_layer_kernel<<<grid, AX_THREADS,
                        AX_ROWS * AX_CHUNK4 * sizeof(float4)>>>(
        x, dmv, dsv, v0p, out, F, n_rows, (long long)out_size);
}